// round 3
// baseline (speedup 1.0000x reference)
#include <cuda_runtime.h>
#include <cuda_bf16.h>

// ---------------------------------------------------------------------------
// out[4096,4096] = x @ sign(W) + b
// hi-pass: bf16(x) @ sign(W)            via mma.sync m16n8k16 bf16
// lo-pass: e4m3((x-hi)*2^6) @ sign*2^-6 via mma.sync m16n8k32 e4m3
// Both accumulate into one fp32 accumulator (scales cancel).
// ---------------------------------------------------------------------------

#define DIMM 4096

constexpr int BM = 128;
constexpr int BN = 256;
constexpr int BK = 64;
constexpr int STAGES = 3;
constexpr int KITERS = DIMM / BK;  // 64

constexpr int AH_BYTES = BM * BK * 2;  // 16384
constexpr int AL_BYTES = BM * BK;      // 8192
constexpr int BH_BYTES = BN * BK * 2;  // 32768
constexpr int BL_BYTES = BN * BK;      // 16384
constexpr int OFF_AL = AH_BYTES;
constexpr int OFF_BH = OFF_AL + AL_BYTES;
constexpr int OFF_BL = OFF_BH + BH_BYTES;
constexpr int STAGE_BYTES = OFF_BL + BL_BYTES;       // 73728
constexpr int SMEM_TOTAL = STAGES * STAGE_BYTES;     // 221184

// Scratch (__device__ globals: allocation-free)
__device__ __align__(1024) __nv_bfloat16 g_S[(size_t)DIMM * DIMM];     // [N][K] sign(W)^T bf16 ±1
__device__ __align__(1024) unsigned char g_S8[(size_t)DIMM * DIMM];    // [N][K] sign(W)^T e4m3 ±2^-6
__device__ __align__(1024) __nv_bfloat16 g_xhi[(size_t)DIMM * DIMM];   // [M][K] bf16(x)
__device__ __align__(1024) unsigned char g_xlo8[(size_t)DIMM * DIMM];  // [M][K] e4m3((x-hi)*64)

// ------------------------- helpers -----------------------------------------

__device__ __forceinline__ unsigned smem_u32(const void* p) {
    unsigned a;
    asm("{ .reg .u64 t; cvta.to.shared.u64 t, %1; cvt.u32.u64 %0, t; }" : "=r"(a) : "l"(p));
    return a;
}
__device__ __forceinline__ unsigned sw128(unsigned off) { return off ^ ((off >> 3) & 0x70); }
__device__ __forceinline__ unsigned sw64(unsigned off) { return off ^ ((off >> 3) & 0x30); }

__device__ __forceinline__ void cp16(unsigned dst, const void* src) {
    asm volatile("cp.async.cg.shared.global [%0], [%1], 16;" ::"r"(dst), "l"(src));
}
__device__ __forceinline__ void ldsm_x4(unsigned& r0, unsigned& r1, unsigned& r2, unsigned& r3,
                                        unsigned addr) {
    asm volatile("ldmatrix.sync.aligned.m8n8.x4.shared.b16 {%0,%1,%2,%3}, [%4];"
                 : "=r"(r0), "=r"(r1), "=r"(r2), "=r"(r3)
                 : "r"(addr));
}
__device__ __forceinline__ void mma_bf16(float* d, const unsigned* a, const unsigned* b) {
    asm volatile(
        "mma.sync.aligned.m16n8k16.row.col.f32.bf16.bf16.f32 "
        "{%0,%1,%2,%3}, {%4,%5,%6,%7}, {%8,%9}, {%0,%1,%2,%3};"
        : "+f"(d[0]), "+f"(d[1]), "+f"(d[2]), "+f"(d[3])
        : "r"(a[0]), "r"(a[1]), "r"(a[2]), "r"(a[3]), "r"(b[0]), "r"(b[1]));
}
__device__ __forceinline__ void mma_fp8(float* d, const unsigned* a, const unsigned* b) {
    asm volatile(
        "mma.sync.aligned.m16n8k32.row.col.f32.e4m3.e4m3.f32 "
        "{%0,%1,%2,%3}, {%4,%5,%6,%7}, {%8,%9}, {%0,%1,%2,%3};"
        : "+f"(d[0]), "+f"(d[1]), "+f"(d[2]), "+f"(d[3])
        : "r"(a[0]), "r"(a[1]), "r"(a[2]), "r"(a[3]), "r"(b[0]), "r"(b[1]));
}
__device__ __forceinline__ unsigned short cvt_e4m3x2(float hi, float lo) {
    unsigned short r;  // low byte <- lo, high byte <- hi
    asm("cvt.rn.satfinite.e4m3x2.f32 %0, %1, %2;" : "=h"(r) : "f"(hi), "f"(lo));
    return r;
}

// ------------------------- prep (one kernel) --------------------------------
// blocks [0,16384): split x -> g_xhi (bf16) + g_xlo8 (e4m3 of residual*64)
// blocks [16384,32768): transposed sign(W) -> g_S (bf16 +-1) + g_S8 (e4m3 +-2^-6)
__global__ void prep_kernel(const float* __restrict__ x, const float* __restrict__ W) {
    __shared__ float t[32][33];
    int bid = blockIdx.x;
    int tid = threadIdx.x;
    if (bid < 16384) {
        size_t i = (size_t)bid * 1024 + tid * 4;
        float4 v = *reinterpret_cast<const float4*>(x + i);
        __nv_bfloat16 h0 = __float2bfloat16(v.x);
        __nv_bfloat16 h1 = __float2bfloat16(v.y);
        __nv_bfloat16 h2 = __float2bfloat16(v.z);
        __nv_bfloat16 h3 = __float2bfloat16(v.w);
        float l0 = (v.x - __bfloat162float(h0)) * 64.f;
        float l1 = (v.y - __bfloat162float(h1)) * 64.f;
        float l2 = (v.z - __bfloat162float(h2)) * 64.f;
        float l3 = (v.w - __bfloat162float(h3)) * 64.f;
        __nv_bfloat162 p;
        __nv_bfloat162* ph = reinterpret_cast<__nv_bfloat162*>(g_xhi + i);
        p.x = h0; p.y = h1; ph[0] = p;
        p.x = h2; p.y = h3; ph[1] = p;
        unsigned packed = (unsigned)cvt_e4m3x2(l1, l0) | ((unsigned)cvt_e4m3x2(l3, l2) << 16);
        *reinterpret_cast<unsigned*>(g_xlo8 + i) = packed;
    } else {
        int b = bid - 16384;
        int nb = (b & 127) * 32, kb = (b >> 7) * 32;
        int tx = tid & 31, ty = tid >> 5;
#pragma unroll
        for (int i = 0; i < 4; i++) {
            float w = W[(size_t)(kb + ty + i * 8) * DIMM + nb + tx];
            t[ty + i * 8][tx] = (w > 0.f) ? 1.f : ((w < 0.f) ? -1.f : 0.f);
        }
        __syncthreads();
#pragma unroll
        for (int i = 0; i < 4; i++) {
            float s = t[tx][ty + i * 8];
            size_t o = (size_t)(nb + ty + i * 8) * DIMM + kb + tx;
            g_S[o] = __float2bfloat16(s);
            g_S8[o] = (s > 0.f) ? 0x08 : ((s < 0.f) ? 0x88 : 0x00);  // +-2^-6 e4m3
        }
    }
}

// ------------------------- GEMM kernel -------------------------------------
// grid = 32*16 = 512 CTAs; 256 threads (8 warps, 2m x 4n), warp tile 64x64.
__global__ void __launch_bounds__(256, 1)
bgemm_kernel(const float* __restrict__ bias, float* __restrict__ out) {
    extern __shared__ char smem[];
    unsigned sb = smem_u32(smem);
    int tid = threadIdx.x;
    int wid = tid >> 5, lane = tid & 31;
    int wm = wid & 1;   // 0..1
    int wn = wid >> 1;  // 0..3
    int m_base = (blockIdx.x & 31) * BM;
    int n_base = (blockIdx.x >> 5) * BN;

    const char* gAh = reinterpret_cast<const char*>(g_xhi) + (size_t)m_base * (DIMM * 2);
    const char* gAl = reinterpret_cast<const char*>(g_xlo8) + (size_t)m_base * DIMM;
    const char* gBh = reinterpret_cast<const char*>(g_S) + (size_t)n_base * (DIMM * 2);
    const char* gBl = reinterpret_cast<const char*>(g_S8) + (size_t)n_base * DIMM;

    // ---- stage loader: 18 cp.async x 16B per thread ----
#define LOAD_STAGE(s, kit)                                                          \
    do {                                                                            \
        unsigned base = sb + (s) * STAGE_BYTES;                                     \
        _Pragma("unroll") for (int p = 0; p < 4; p++) {   /* A_hi 16KB */           \
            int idx = p * 256 + tid;                                                \
            int row = idx >> 3, colb = (idx & 7) * 16;                              \
            cp16(base + sw128((unsigned)(row * 128 + colb)),                        \
                 gAh + (size_t)(kit) * 128 + (size_t)row * (DIMM * 2) + colb);      \
        }                                                                           \
        _Pragma("unroll") for (int p = 0; p < 2; p++) {   /* A_lo 8KB */            \
            int idx = p * 256 + tid;                                                \
            int row = idx >> 2, colb = (idx & 3) * 16;                              \
            cp16(base + OFF_AL + sw64((unsigned)(row * 64 + colb)),                 \
                 gAl + (size_t)(kit) * 64 + (size_t)row * DIMM + colb);             \
        }                                                                           \
        _Pragma("unroll") for (int p = 0; p < 8; p++) {   /* B_hi 32KB */           \
            int idx = p * 256 + tid;                                                \
            int row = idx >> 3, colb = (idx & 7) * 16;                              \
            cp16(base + OFF_BH + sw128((unsigned)(row * 128 + colb)),               \
                 gBh + (size_t)(kit) * 128 + (size_t)row * (DIMM * 2) + colb);      \
        }                                                                           \
        _Pragma("unroll") for (int p = 0; p < 4; p++) {   /* B_lo 16KB */           \
            int idx = p * 256 + tid;                                                \
            int row = idx >> 2, colb = (idx & 3) * 16;                              \
            cp16(base + OFF_BL + sw64((unsigned)(row * 64 + colb)),                 \
                 gBl + (size_t)(kit) * 64 + (size_t)row * DIMM + colb);             \
        }                                                                           \
        asm volatile("cp.async.commit_group;");                                     \
    } while (0)

    LOAD_STAGE(0, 0);
    LOAD_STAGE(1, 1);

    float acc[4][8][4];
#pragma unroll
    for (int mi = 0; mi < 4; mi++)
#pragma unroll
        for (int ni = 0; ni < 8; ni++)
#pragma unroll
            for (int c = 0; c < 4; c++) acc[mi][ni][c] = 0.f;

    // ldmatrix lane patterns
    int lr = lane & 15;                      // row within 16
    int hc = lane >> 4;                      // 16B column group (0/1)
    int brow = ((lane >> 4) << 3) + (lane & 7);  // b16 B row pattern
    int bc = (lane >> 3) & 1;                // b16 B column half

    int s = 0;
#pragma unroll 1
    for (int kit = 0; kit < KITERS; kit++) {
        if (kit + 1 < KITERS)
            asm volatile("cp.async.wait_group 1;" ::: "memory");
        else
            asm volatile("cp.async.wait_group 0;" ::: "memory");
        __syncthreads();

        if (kit + 2 < KITERS) LOAD_STAGE((s + 2) % STAGES, kit + 2);

        unsigned sAh = sb + s * STAGE_BYTES;
        unsigned sAl = sAh + OFF_AL;
        unsigned sBh = sAh + OFF_BH;
        unsigned sBl = sAh + OFF_BL;

#pragma unroll
        for (int kt = 0; kt < 4; kt++) {
            // ---- hi pass (bf16 k16) ----
            unsigned a[4][4], bfr[8][2];
#pragma unroll
            for (int mi = 0; mi < 4; mi++) {
                int mrow = wm * 64 + mi * 16 + lr;
                ldsm_x4(a[mi][0], a[mi][1], a[mi][2], a[mi][3],
                        sAh + sw128((unsigned)(mrow * 128 + kt * 32 + hc * 16)));
            }
#pragma unroll
            for (int nb = 0; nb < 4; nb++) {
                int nrow = wn * 64 + nb * 16 + brow;
                ldsm_x4(bfr[2 * nb][0], bfr[2 * nb][1], bfr[2 * nb + 1][0], bfr[2 * nb + 1][1],
                        sBh + sw128((unsigned)(nrow * 128 + kt * 32 + bc * 16)));
            }
#pragma unroll
            for (int ni = 0; ni < 8; ni++)
#pragma unroll
                for (int mi = 0; mi < 4; mi++) mma_bf16(acc[mi][ni], a[mi], bfr[ni]);

            // ---- lo pass (e4m3 k32) every other kt ----
            if (kt & 1) {
                int kt2 = kt >> 1;
                unsigned al[4][4], bl[8][2];
#pragma unroll
                for (int mi = 0; mi < 4; mi++) {
                    int mrow = wm * 64 + mi * 16 + lr;
                    ldsm_x4(al[mi][0], al[mi][1], al[mi][2], al[mi][3],
                            sAl + sw64((unsigned)(mrow * 64 + kt2 * 32 + hc * 16)));
                }
#pragma unroll
                for (int nb = 0; nb < 4; nb++) {
                    int nrow = wn * 64 + nb * 16 + lr;
                    unsigned r0, r1, r2, r3;
                    ldsm_x4(r0, r1, r2, r3,
                            sBl + sw64((unsigned)(nrow * 64 + kt2 * 32 + hc * 16)));
                    bl[2 * nb][0] = r0; bl[2 * nb][1] = r2;      // n0-7:  k0-15B, k16-31B
                    bl[2 * nb + 1][0] = r1; bl[2 * nb + 1][1] = r3;  // n8-15
                }
#pragma unroll
                for (int ni = 0; ni < 8; ni++)
#pragma unroll
                    for (int mi = 0; mi < 4; mi++) mma_fp8(acc[mi][ni], al[mi], bl[ni]);
            }
        }
        s = (s + 1) % STAGES;
    }

    // ------------------ epilogue ------------------
    int qrow = lane >> 2;
    int qcol = (lane & 3) * 2;
#pragma unroll
    for (int mi = 0; mi < 4; mi++) {
        int r0 = m_base + wm * 64 + mi * 16 + qrow;
#pragma unroll
        for (int ni = 0; ni < 8; ni++) {
            int c = n_base + wn * 64 + ni * 8 + qcol;
            float2 bb = *reinterpret_cast<const float2*>(bias + c);
            float2 v0, v1;
            v0.x = acc[mi][ni][0] + bb.x;
            v0.y = acc[mi][ni][1] + bb.y;
            v1.x = acc[mi][ni][2] + bb.x;
            v1.y = acc[mi][ni][3] + bb.y;
            *reinterpret_cast<float2*>(out + (size_t)r0 * DIMM + c) = v0;
            *reinterpret_cast<float2*>(out + (size_t)(r0 + 8) * DIMM + c) = v1;
        }
    }
#undef LOAD_STAGE
}

// ------------------------- launch ------------------------------------------

extern "C" void kernel_launch(void* const* d_in, const int* in_sizes, int n_in,
                              void* d_out, int out_size) {
    const float* x = (const float*)d_in[0];
    const float* W = (const float*)d_in[1];
    const float* b = (const float*)d_in[2];
    float* out = (float*)d_out;

    cudaFuncSetAttribute(bgemm_kernel, cudaFuncAttributeMaxDynamicSharedMemorySize, SMEM_TOTAL);

    prep_kernel<<<32768, 256>>>(x, W);
    bgemm_kernel<<<(DIMM / BM) * (DIMM / BN), 256, SMEM_TOTAL>>>(b, out);
}

// round 4
// speedup vs baseline: 2.6121x; 2.6121x over previous
#include <cuda_runtime.h>
#include <cuda_fp16.h>

// ---------------------------------------------------------------------------
// out[4096,4096] = x @ sign(W) + b
// Single-pass fp16: A = fp16(x) (11 mantissa bits -> norm rel_err ~1.5e-4),
// B = sign(W)^T as fp16 (+-1 exact), fp32 accumulator via mma.sync m16n8k16.
// ---------------------------------------------------------------------------

#define DIMM 4096

constexpr int BM = 128;
constexpr int BN = 128;
constexpr int BK = 64;
constexpr int STAGES = 3;
constexpr int KITERS = DIMM / BK;                 // 64
constexpr int TILE_BYTES = 128 * 64 * 2;          // 16384
constexpr int STAGE_BYTES = 2 * TILE_BYTES;       // 32768 (A + B)
constexpr int SMEM_TOTAL = STAGES * STAGE_BYTES;  // 98304

// Scratch (__device__ globals: allocation-free)
__device__ __align__(1024) __half g_ST[(size_t)DIMM * DIMM];  // [N][K] sign(W)^T fp16
__device__ __align__(1024) __half g_xh[(size_t)DIMM * DIMM];  // [M][K] fp16(x)

// ------------------------- helpers -----------------------------------------

__device__ __forceinline__ unsigned smem_u32(const void* p) {
    unsigned a;
    asm("{ .reg .u64 t; cvta.to.shared.u64 t, %1; cvt.u32.u64 %0, t; }" : "=r"(a) : "l"(p));
    return a;
}
__device__ __forceinline__ unsigned sw128(unsigned off) { return off ^ ((off >> 3) & 0x70); }

__device__ __forceinline__ void cp16(unsigned dst, const void* src) {
    asm volatile("cp.async.cg.shared.global [%0], [%1], 16;" ::"r"(dst), "l"(src));
}
__device__ __forceinline__ void ldsm_x4(unsigned& r0, unsigned& r1, unsigned& r2, unsigned& r3,
                                        unsigned addr) {
    asm volatile("ldmatrix.sync.aligned.m8n8.x4.shared.b16 {%0,%1,%2,%3}, [%4];"
                 : "=r"(r0), "=r"(r1), "=r"(r2), "=r"(r3)
                 : "r"(addr));
}
__device__ __forceinline__ void mma_f16(float* d, const unsigned* a, const unsigned* b) {
    asm volatile(
        "mma.sync.aligned.m16n8k16.row.col.f32.f16.f16.f32 "
        "{%0,%1,%2,%3}, {%4,%5,%6,%7}, {%8,%9}, {%0,%1,%2,%3};"
        : "+f"(d[0]), "+f"(d[1]), "+f"(d[2]), "+f"(d[3])
        : "r"(a[0]), "r"(a[1]), "r"(a[2]), "r"(a[3]), "r"(b[0]), "r"(b[1]));
}

// ------------------------- prep (one kernel) --------------------------------
// blocks [0,16384): x -> fp16                (1024 elements per block)
// blocks [16384,32768): W -> transposed sign fp16 (32x32 tile per block)
__global__ void prep_kernel(const float* __restrict__ x, const float* __restrict__ W) {
    __shared__ float t[32][33];
    int bid = blockIdx.x;
    int tid = threadIdx.x;
    if (bid < 16384) {
        size_t i = (size_t)bid * 1024 + tid * 4;
        float4 v = *reinterpret_cast<const float4*>(x + i);
        __half2* ph = reinterpret_cast<__half2*>(g_xh + i);
        ph[0] = __floats2half2_rn(v.x, v.y);
        ph[1] = __floats2half2_rn(v.z, v.w);
    } else {
        int b = bid - 16384;
        int nb = (b & 127) * 32, kb = (b >> 7) * 32;
        int tx = tid & 31, ty = tid >> 5;
#pragma unroll
        for (int i = 0; i < 4; i++) {
            float w = W[(size_t)(kb + ty + i * 8) * DIMM + nb + tx];
            t[ty + i * 8][tx] = (w > 0.f) ? 1.f : ((w < 0.f) ? -1.f : 0.f);
        }
        __syncthreads();
#pragma unroll
        for (int i = 0; i < 4; i++) {
            g_ST[(size_t)(nb + ty + i * 8) * DIMM + kb + tx] = __float2half(t[tx][ty + i * 8]);
        }
    }
}

// ------------------------- GEMM kernel -------------------------------------
// grid = 32*32 = 1024 CTAs; 256 threads (8 warps, 4m x 2n), warp tile 32x64.
// 2 CTAs/SM (96KB smem, <=128 regs).
__global__ void __launch_bounds__(256, 2)
bgemm_kernel(const float* __restrict__ bias, float* __restrict__ out) {
    extern __shared__ char smem[];
    unsigned sb = smem_u32(smem);
    int tid = threadIdx.x;
    int wid = tid >> 5, lane = tid & 31;
    int wm = wid & 3;   // warp m index 0..3
    int wn = wid >> 2;  // warp n index 0..1
    int m_base = (blockIdx.x & 31) * BM;
    int n_base = (blockIdx.x >> 5) * BN;

    const char* gA = reinterpret_cast<const char*>(g_xh) + (size_t)m_base * (DIMM * 2);
    const char* gB = reinterpret_cast<const char*>(g_ST) + (size_t)n_base * (DIMM * 2);

    // per-thread cp.async offsets (4 passes per 16KB tile)
    unsigned s_off[4];
    size_t g_off[4];
#pragma unroll
    for (int p = 0; p < 4; p++) {
        int idx = p * 256 + tid;
        int row = idx >> 3, colb = (idx & 7) * 16;
        s_off[p] = sw128((unsigned)(row * 128 + colb));
        g_off[p] = (size_t)row * (DIMM * 2) + colb;
    }

#define LOAD_STAGE(s, kit)                                              \
    do {                                                                \
        unsigned base = sb + (s) * STAGE_BYTES;                         \
        size_t kb = (size_t)(kit) * (BK * 2);                           \
        _Pragma("unroll") for (int p = 0; p < 4; p++) {                 \
            cp16(base + s_off[p], gA + kb + g_off[p]);                  \
            cp16(base + TILE_BYTES + s_off[p], gB + kb + g_off[p]);     \
        }                                                               \
        asm volatile("cp.async.commit_group;");                         \
    } while (0)

    LOAD_STAGE(0, 0);
    LOAD_STAGE(1, 1);

    float acc[2][8][4];
#pragma unroll
    for (int mi = 0; mi < 2; mi++)
#pragma unroll
        for (int ni = 0; ni < 8; ni++)
#pragma unroll
            for (int c = 0; c < 4; c++) acc[mi][ni][c] = 0.f;

    // ldmatrix lane patterns
    int a_row = lane & 15;
    int a_colb = (lane >> 4) * 16;
    int b_row = ((lane >> 4) << 3) + (lane & 7);
    int b_colb = ((lane >> 3) & 1) * 16;

    int s = 0;
#pragma unroll 1
    for (int kit = 0; kit < KITERS; kit++) {
        if (kit + 1 < KITERS)
            asm volatile("cp.async.wait_group 1;" ::: "memory");
        else
            asm volatile("cp.async.wait_group 0;" ::: "memory");
        __syncthreads();

        if (kit + 2 < KITERS) LOAD_STAGE((s + 2) % STAGES, kit + 2);

        unsigned sA = sb + s * STAGE_BYTES;
        unsigned sB = sA + TILE_BYTES;

#pragma unroll
        for (int kt = 0; kt < 4; kt++) {
            unsigned bfr[8][2];
#pragma unroll
            for (int nb = 0; nb < 4; nb++) {
                int nrow = wn * 64 + nb * 16 + b_row;
                ldsm_x4(bfr[2 * nb][0], bfr[2 * nb][1], bfr[2 * nb + 1][0], bfr[2 * nb + 1][1],
                        sB + sw128((unsigned)(nrow * 128 + kt * 32 + b_colb)));
            }
            unsigned a[2][4];
#pragma unroll
            for (int mi = 0; mi < 2; mi++) {
                int mrow = wm * 32 + mi * 16 + a_row;
                ldsm_x4(a[mi][0], a[mi][1], a[mi][2], a[mi][3],
                        sA + sw128((unsigned)(mrow * 128 + kt * 32 + a_colb)));
            }
#pragma unroll
            for (int mi = 0; mi < 2; mi++)
#pragma unroll
                for (int ni = 0; ni < 8; ni++) mma_f16(acc[mi][ni], a[mi], bfr[ni]);
        }
        s = (s + 1) % STAGES;
    }

    // ------------------ epilogue ------------------
    int qrow = lane >> 2;
    int qcol = (lane & 3) * 2;
#pragma unroll
    for (int mi = 0; mi < 2; mi++) {
        int r0 = m_base + wm * 32 + mi * 16 + qrow;
#pragma unroll
        for (int ni = 0; ni < 8; ni++) {
            int c = n_base + wn * 64 + ni * 8 + qcol;
            float2 bb = *reinterpret_cast<const float2*>(bias + c);
            float2 v0, v1;
            v0.x = acc[mi][ni][0] + bb.x;
            v0.y = acc[mi][ni][1] + bb.y;
            v1.x = acc[mi][ni][2] + bb.x;
            v1.y = acc[mi][ni][3] + bb.y;
            *reinterpret_cast<float2*>(out + (size_t)r0 * DIMM + c) = v0;
            *reinterpret_cast<float2*>(out + (size_t)(r0 + 8) * DIMM + c) = v1;
        }
    }
#undef LOAD_STAGE
}

// ------------------------- launch ------------------------------------------

extern "C" void kernel_launch(void* const* d_in, const int* in_sizes, int n_in,
                              void* d_out, int out_size) {
    const float* x = (const float*)d_in[0];
    const float* W = (const float*)d_in[1];
    const float* b = (const float*)d_in[2];
    float* out = (float*)d_out;

    cudaFuncSetAttribute(bgemm_kernel, cudaFuncAttributeMaxDynamicSharedMemorySize, SMEM_TOTAL);

    prep_kernel<<<32768, 256>>>(x, W);
    bgemm_kernel<<<(DIMM / BM) * (DIMM / BN), 256, SMEM_TOTAL>>>(b, out);
}